// round 13
// baseline (speedup 1.0000x reference)
#include <cuda_runtime.h>
#include <cstdint>

// GCN 2-layer: out = log_softmax( A * relu(A * (x@W1) + b1) @ W2 + b2 )
// CSR gather aggregation (no atomics), GEMMs via sm_103a packed fma.rn.f32x2
// with pre-duplicated weight pairs (no pack MOVs) + LDS.128 row-pair loads.

#define MAXN 100000
#define MAXE 1600000
#define DEGB 512            // extra blocks appended to gemm1 launch for degree histogram

__device__ __align__(16) float g_dinv[MAXN];
__device__ int   g_cnt [MAXN];
__device__ int   g_row [MAXN];
__device__ int   g_cur [MAXN];
__device__ int   g_bsum[128];
__device__ __align__(16) int2  g_edge[MAXE];        // {src, w_bits} sorted by dst
__device__ __align__(16) float g_h  [MAXN * 128];   // x@W1
__device__ __align__(16) float g_hb [MAXN * 128];   // relu(A*h + b1)
__device__ __align__(16) float g_h2 [MAXN * 64];    // hb@W2
__device__ __align__(16) float2 g_w1d[128 * 128];   // W1 with each element duplicated (w,w)
__device__ __align__(16) float2 g_w2d[128 * 64];    // W2 duplicated
__device__ int g_is32;

__device__ __forceinline__ int edge_at(const void* ei, long long pos, int is32) {
    if (is32) return ((const int*)ei)[pos];
    return (int)(((const long long*)ei)[pos]);
}

// ---- packed f32x2 helpers (sm_103a FFMA2) ----
__device__ __forceinline__ void fma2(unsigned long long& d, unsigned long long a, unsigned long long b) {
    asm("fma.rn.f32x2 %0, %1, %2, %0;" : "+l"(d) : "l"(a), "l"(b));
}
__device__ __forceinline__ float2 upk2(unsigned long long v) {
    float2 f; asm("mov.b64 {%0,%1}, %2;" : "=f"(f.x), "=f"(f.y) : "l"(v)); return f;
}

// ------------------------------------------------------------ init / dtype detect
__global__ void k_init(int n) {
    int i = blockIdx.x * blockDim.x + threadIdx.x;
    if (i < n) g_cnt[i] = 0;
    if (i == 0) g_is32 = 0;
}

// Sample 4096 odd words: int64 ids (<2^31) -> all zero; int32 -> random nonzero.
__global__ void k_detect(const unsigned int* e, int nwords) {
    int i = blockIdx.x * blockDim.x + threadIdx.x;
    int idx = 2 * i + 1;
    if (i < 4096 && idx < nwords && e[idx] != 0u) atomicOr(&g_is32, 1);
}

// ------------------------------------------------------------ duplicate W1/W2 into (w,w) pairs
__global__ void k_prepw(const float* __restrict__ W1, const float* __restrict__ W2) {
    int i = blockIdx.x * blockDim.x + threadIdx.x;
    if (i < 16384)              { float w = W1[i];         g_w1d[i]         = make_float2(w, w); }
    else if (i < 16384 + 8192)  { float w = W2[i - 16384]; g_w2d[i - 16384] = make_float2(w, w); }
}

// ------------------------------------------------------------ prefix scan
__global__ void k_scan1(int n) {
    __shared__ int sm[1024];
    int tid = threadIdx.x;
    int i = blockIdx.x * 1024 + tid;
    int v = (i < n) ? g_cnt[i] : 0;
    sm[tid] = v;
    __syncthreads();
#pragma unroll
    for (int o = 1; o < 1024; o <<= 1) {
        int t = (tid >= o) ? sm[tid - o] : 0;
        __syncthreads();
        sm[tid] += t;
        __syncthreads();
    }
    if (i < n) g_row[i] = sm[tid] - v;
    if (tid == 1023) g_bsum[blockIdx.x] = sm[tid];
}

__global__ void k_scan2(int nb) {
    if (threadIdx.x == 0) {
        int acc = 0;
        for (int b = 0; b < nb; b++) { int t = g_bsum[b]; g_bsum[b] = acc; acc += t; }
    }
}

__global__ void k_scan3(int n) {
    int i = blockIdx.x * blockDim.x + threadIdx.x;
    if (i >= n) return;
    int r = g_row[i] + g_bsum[i >> 10];
    g_row[i] = r;
    g_cur[i] = r;
    g_dinv[i] = rsqrtf(1.0f + (float)g_cnt[i]);
}

// ------------------------------------------------------------ CSR fill
__global__ void k_fill(const void* ei, int E) {
    int e = blockIdx.x * blockDim.x + threadIdx.x;
    if (e >= E) return;
    int is32 = g_is32;
    int s = edge_at(ei, e, is32);
    int d = edge_at(ei, (long long)E + e, is32);
    int pos = atomicAdd(&g_cur[d], 1);
    float w = g_dinv[s] * g_dinv[d];
    g_edge[pos] = make_int2(s, __float_as_int(w));
}

#define XS(k, r) xs[(k) * 68 + (r)]

// ------------------------------------------------------------ fused GEMM1 + degree histogram
// Blocks [0, g1b): h = x @ W1 (64-row k-major tile, duplicated-W FFMA2).
// Blocks [g1b, +DEGB): grid-stride degree histogram (independent).
__global__ void k_gemm1deg(const float* __restrict__ x,
                           const void* ei, int N, int E, int g1b) {
    if (blockIdx.x >= g1b) {
        int is32 = g_is32;
        int base   = (blockIdx.x - g1b) * blockDim.x + threadIdx.x;
        int stride = DEGB * blockDim.x;
        for (int i = base; i < E; i += stride) {
            int d = edge_at(ei, (long long)E + i, is32);
            atomicAdd(&g_cnt[d], 1);
        }
        return;
    }

    __shared__ float xs[128 * 68];     // [k][row], stride 68 (16B-aligned row-pairs)
    int row0 = blockIdx.x * 64;
    int tid  = threadIdx.x;

    for (int i = tid; i < 64 * 128; i += 256) {
        int k = i & 127, r = i >> 7;
        int gr = row0 + r;
        XS(k, r) = (gr < N) ? x[(size_t)gr * 128 + k] : 0.f;
    }
    __syncthreads();

    int tx = tid & 31;       // cols tx*4..tx*4+3
    int ty = tid >> 5;       // rows ty*8..ty*8+7 (4 row-pairs)
    unsigned long long acc[4][4];
#pragma unroll
    for (int rp = 0; rp < 4; rp++)
#pragma unroll
        for (int c = 0; c < 4; c++) acc[rp][c] = 0ull;

    const ulonglong2* __restrict__ Wd = (const ulonglong2*)g_w1d;  // 2 (w,w) pairs per elem
#pragma unroll 4
    for (int k = 0; k < 128; k++) {
        ulonglong2 wa = __ldg(&Wd[k * 64 + 2 * tx]);       // (w0,w0),(w1,w1)
        ulonglong2 wb = __ldg(&Wd[k * 64 + 2 * tx + 1]);   // (w2,w2),(w3,w3)
        ulonglong2 x01 = *(const ulonglong2*)&XS(k, ty * 8);      // row-pairs 0,1
        ulonglong2 x23 = *(const ulonglong2*)&XS(k, ty * 8 + 4);  // row-pairs 2,3
        fma2(acc[0][0], x01.x, wa.x); fma2(acc[0][1], x01.x, wa.y);
        fma2(acc[0][2], x01.x, wb.x); fma2(acc[0][3], x01.x, wb.y);
        fma2(acc[1][0], x01.y, wa.x); fma2(acc[1][1], x01.y, wa.y);
        fma2(acc[1][2], x01.y, wb.x); fma2(acc[1][3], x01.y, wb.y);
        fma2(acc[2][0], x23.x, wa.x); fma2(acc[2][1], x23.x, wa.y);
        fma2(acc[2][2], x23.x, wb.x); fma2(acc[2][3], x23.x, wb.y);
        fma2(acc[3][0], x23.y, wa.x); fma2(acc[3][1], x23.y, wa.y);
        fma2(acc[3][2], x23.y, wb.x); fma2(acc[3][3], x23.y, wb.y);
    }

    float4* h4 = (float4*)g_h;
#pragma unroll
    for (int rp = 0; rp < 4; rp++) {
        float2 c0 = upk2(acc[rp][0]), c1 = upk2(acc[rp][1]);
        float2 c2 = upk2(acc[rp][2]), c3 = upk2(acc[rp][3]);
        int gr0 = row0 + ty * 8 + rp * 2;
        if (gr0 < N)
            h4[(size_t)gr0 * 32 + tx] = make_float4(c0.x, c1.x, c2.x, c3.x);
        if (gr0 + 1 < N)
            h4[(size_t)(gr0 + 1) * 32 + tx] = make_float4(c0.y, c1.y, c2.y, c3.y);
    }
}

// ------------------------------------------------------------ agg layer 1 (warp/node, shfl-batched)
__global__ void k_agg1(const float* __restrict__ b1, int N) {
    int lane = threadIdx.x & 31;
    int node = (blockIdx.x * blockDim.x + threadIdx.x) >> 5;
    if (node >= N) return;
    const float4* __restrict__ h4 = (const float4*)g_h;

    float di = g_dinv[node];
    float4 acc = h4[(size_t)node * 32 + lane];
    float sw = di * di;
    acc.x *= sw; acc.y *= sw; acc.z *= sw; acc.w *= sw;

    int beg = g_row[node];
    int deg = g_cnt[node];

    for (int base = 0; base < deg; base += 32) {
        int rem = deg - base;
        int m = rem < 32 ? rem : 32;
        int2 ew = make_int2(0, 0);
        if (lane < m) ew = __ldg(&g_edge[beg + base + lane]);
#pragma unroll 8
        for (int t = 0; t < m; t++) {
            int   s = __shfl_sync(0xFFFFFFFFu, ew.x, t);
            float w = __int_as_float(__shfl_sync(0xFFFFFFFFu, ew.y, t));
            float4 v = h4[(size_t)s * 32 + lane];
            acc.x += v.x * w; acc.y += v.y * w;
            acc.z += v.z * w; acc.w += v.w * w;
        }
    }
    float4 b = ((const float4*)b1)[lane];
    acc.x = fmaxf(acc.x + b.x, 0.f);
    acc.y = fmaxf(acc.y + b.y, 0.f);
    acc.z = fmaxf(acc.z + b.z, 0.f);
    acc.w = fmaxf(acc.w + b.w, 0.f);
    ((float4*)g_hb)[(size_t)node * 32 + lane] = acc;
}

// ------------------------------------------------------------ GEMM2: h2 = hb @ W2 [N,128]x[128,64]
__global__ void k_gemm2(int N) {
    __shared__ float xs[128 * 68];
    int row0 = blockIdx.x * 64;
    int tid  = threadIdx.x;

    for (int i = tid; i < 64 * 128; i += 256) {
        int k = i & 127, r = i >> 7;
        int gr = row0 + r;
        XS(k, r) = (gr < N) ? g_hb[(size_t)gr * 128 + k] : 0.f;
    }
    __syncthreads();

    int tx = tid & 15;       // cols tx*4..tx*4+3 (64 cols)
    int ty = tid >> 4;       // rows ty*4..ty*4+3 (2 row-pairs)
    unsigned long long acc[2][4];
#pragma unroll
    for (int rp = 0; rp < 2; rp++)
#pragma unroll
        for (int c = 0; c < 4; c++) acc[rp][c] = 0ull;

    const ulonglong2* __restrict__ Wd = (const ulonglong2*)g_w2d;
#pragma unroll 4
    for (int k = 0; k < 128; k++) {
        ulonglong2 wa = __ldg(&Wd[k * 32 + 2 * tx]);
        ulonglong2 wb = __ldg(&Wd[k * 32 + 2 * tx + 1]);
        ulonglong2 x01 = *(const ulonglong2*)&XS(k, ty * 4);   // row-pairs 0,1
        fma2(acc[0][0], x01.x, wa.x); fma2(acc[0][1], x01.x, wa.y);
        fma2(acc[0][2], x01.x, wb.x); fma2(acc[0][3], x01.x, wb.y);
        fma2(acc[1][0], x01.y, wa.x); fma2(acc[1][1], x01.y, wa.y);
        fma2(acc[1][2], x01.y, wb.x); fma2(acc[1][3], x01.y, wb.y);
    }

    float4* o4 = (float4*)g_h2;
#pragma unroll
    for (int rp = 0; rp < 2; rp++) {
        float2 c0 = upk2(acc[rp][0]), c1 = upk2(acc[rp][1]);
        float2 c2 = upk2(acc[rp][2]), c3 = upk2(acc[rp][3]);
        int gr0 = row0 + ty * 4 + rp * 2;
        if (gr0 < N)
            o4[(size_t)gr0 * 16 + tx] = make_float4(c0.x, c1.x, c2.x, c3.x);
        if (gr0 + 1 < N)
            o4[(size_t)(gr0 + 1) * 16 + tx] = make_float4(c0.y, c1.y, c2.y, c3.y);
    }
}

// ------------------------------------------------------------ agg layer 2: half-warp per node + log_softmax
__global__ void k_agg2(const float* __restrict__ b2, float* __restrict__ out, int N) {
    int tid  = threadIdx.x;
    int lane = tid & 31;
    int half = lane >> 4;
    int hl   = lane & 15;
    int node = (((blockIdx.x * blockDim.x + tid) >> 5) << 1) + half;
    if (node >= N) return;
    unsigned mask = half ? 0xFFFF0000u : 0x0000FFFFu;
    const float4* __restrict__ h4 = (const float4*)g_h2;   // row = 16 float4

    float di = g_dinv[node];
    float4 acc = h4[(size_t)node * 16 + hl];
    float sw = di * di;
    acc.x *= sw; acc.y *= sw; acc.z *= sw; acc.w *= sw;

    int beg = g_row[node];
    int deg = g_cnt[node];
    int src0 = half << 4;

    for (int base = 0; base < deg; base += 16) {
        int rem = deg - base;
        int m = rem < 16 ? rem : 16;
        int2 ew = make_int2(0, 0);
        if (hl < m) ew = __ldg(&g_edge[beg + base + hl]);
#pragma unroll 4
        for (int t = 0; t < m; t++) {
            int   s = __shfl_sync(mask, ew.x, src0 + t);
            float w = __int_as_float(__shfl_sync(mask, ew.y, src0 + t));
            float4 v = h4[(size_t)s * 16 + hl];
            acc.x += v.x * w; acc.y += v.y * w;
            acc.z += v.z * w; acc.w += v.w * w;
        }
    }
    float4 b = ((const float4*)b2)[hl];
    acc.x += b.x; acc.y += b.y; acc.z += b.z; acc.w += b.w;

    float m1 = fmaxf(fmaxf(acc.x, acc.y), fmaxf(acc.z, acc.w));
#pragma unroll
    for (int o = 8; o; o >>= 1) m1 = fmaxf(m1, __shfl_xor_sync(mask, m1, o));
    float s = __expf(acc.x - m1) + __expf(acc.y - m1) + __expf(acc.z - m1) + __expf(acc.w - m1);
#pragma unroll
    for (int o = 8; o; o >>= 1) s += __shfl_xor_sync(mask, s, o);
    float lg = m1 + logf(s);
    ((float4*)out)[(size_t)node * 16 + hl] =
        make_float4(acc.x - lg, acc.y - lg, acc.z - lg, acc.w - lg);
}

// ============================================================ launch
extern "C" void kernel_launch(void* const* d_in, const int* in_sizes, int n_in,
                              void* d_out, int out_size) {
    const float* x  = (const float*)d_in[0];
    const void*  ei = d_in[1];
    const float* W1 = (const float*)d_in[2];
    const float* b1 = (const float*)d_in[3];
    const float* W2 = (const float*)d_in[4];
    const float* b2 = (const float*)d_in[5];
    float* out = (float*)d_out;

    int N = in_sizes[0] / 128;       // 100000
    int E = in_sizes[1] / 2;         // 1600000
    int nscanblk = (N + 1023) / 1024;
    int g1b = (N + 63) / 64;

    // Launch index 3 (ncu's capture slot) = fused GEMM1+deg.
    k_init     <<<(N + 255) / 256, 256>>>(N);
    k_detect   <<<16, 256>>>((const unsigned int*)ei, 2 * E);
    k_prepw    <<<96, 256>>>(W1, W2);
    k_gemm1deg <<<g1b + DEGB, 256>>>(x, ei, N, E, g1b);
    k_scan1    <<<nscanblk, 1024>>>(N);
    k_scan2    <<<1, 32>>>(nscanblk);
    k_scan3    <<<(N + 255) / 256, 256>>>(N);
    k_fill     <<<(E + 255) / 256, 256>>>(ei, E);
    k_agg1     <<<(N + 7) / 8, 256>>>(b1, N);
    k_gemm2    <<<(N + 63) / 64, 256>>>(N);
    k_agg2     <<<(N / 2 + 7) / 8, 256>>>(b2, out, N);
}

// round 15
// speedup vs baseline: 1.5769x; 1.5769x over previous
#include <cuda_runtime.h>
#include <cuda_fp16.h>
#include <cstdint>

// GCN 2-layer: out = log_softmax( A * relu(A * (x@W1) + b1) @ W2 + b2 )
// CSR gather aggregation (no atomics), GEMMs via sm_103a packed fma.rn.f32x2.
// Gather sources (g_h, g_h2) stored fp16 to halve agg L2 traffic; all arithmetic fp32.

#define MAXN 100000
#define MAXE 1600000
#define DEGB 512            // extra blocks appended to gemm1 launch for degree histogram

__device__ __align__(16) float g_dinv[MAXN];
__device__ int   g_cnt [MAXN];
__device__ int   g_row [MAXN];
__device__ int   g_cur [MAXN];
__device__ int   g_bsum[128];
__device__ __align__(16) int2   g_edge[MAXE];        // {src, w_bits} sorted by dst
__device__ __align__(16) __half g_h  [MAXN * 128];   // x@W1 (fp16 gather source)
__device__ __align__(16) float  g_hb [MAXN * 128];   // relu(A*h + b1), fp32 (gemm2 input)
__device__ __align__(16) __half g_h2 [MAXN * 64];    // hb@W2 (fp16 gather source)
__device__ int g_is32;

__device__ __forceinline__ int edge_at(const void* ei, long long pos, int is32) {
    if (is32) return ((const int*)ei)[pos];
    return (int)(((const long long*)ei)[pos]);
}

// ---- packed f32x2 helpers (sm_103a FFMA2) ----
__device__ __forceinline__ void fma2(unsigned long long& d, unsigned long long a, unsigned long long b) {
    asm("fma.rn.f32x2 %0, %1, %2, %0;" : "+l"(d) : "l"(a), "l"(b));
}
__device__ __forceinline__ unsigned long long pk2(float lo, float hi) {
    unsigned long long r; asm("mov.b64 %0, {%1,%2};" : "=l"(r) : "f"(lo), "f"(hi)); return r;
}
__device__ __forceinline__ float2 upk2(unsigned long long v) {
    float2 f; asm("mov.b64 {%0,%1}, %2;" : "=f"(f.x), "=f"(f.y) : "l"(v)); return f;
}
// unpack uint2 (4 halves) -> float4
__device__ __forceinline__ float4 h4f(uint2 v) {
    float2 a = __half22float2(*(half2*)&v.x);
    float2 b = __half22float2(*(half2*)&v.y);
    return make_float4(a.x, a.y, b.x, b.y);
}

// ------------------------------------------------------------ init / dtype detect
__global__ void k_init(int n) {
    int i = blockIdx.x * blockDim.x + threadIdx.x;
    if (i < n) g_cnt[i] = 0;
    if (i == 0) g_is32 = 0;
}

// Sample 4096 odd words: int64 ids (<2^31) -> all zero; int32 -> random nonzero.
__global__ void k_detect(const unsigned int* e, int nwords) {
    int i = blockIdx.x * blockDim.x + threadIdx.x;
    int idx = 2 * i + 1;
    if (i < 4096 && idx < nwords && e[idx] != 0u) atomicOr(&g_is32, 1);
}

// ------------------------------------------------------------ prefix scan
__global__ void k_scan1(int n) {
    __shared__ int sm[1024];
    int tid = threadIdx.x;
    int i = blockIdx.x * 1024 + tid;
    int v = (i < n) ? g_cnt[i] : 0;
    sm[tid] = v;
    __syncthreads();
#pragma unroll
    for (int o = 1; o < 1024; o <<= 1) {
        int t = (tid >= o) ? sm[tid - o] : 0;
        __syncthreads();
        sm[tid] += t;
        __syncthreads();
    }
    if (i < n) g_row[i] = sm[tid] - v;
    if (tid == 1023) g_bsum[blockIdx.x] = sm[tid];
}

__global__ void k_scan2(int nb) {
    if (threadIdx.x == 0) {
        int acc = 0;
        for (int b = 0; b < nb; b++) { int t = g_bsum[b]; g_bsum[b] = acc; acc += t; }
    }
}

__global__ void k_scan3(int n) {
    int i = blockIdx.x * blockDim.x + threadIdx.x;
    if (i >= n) return;
    int r = g_row[i] + g_bsum[i >> 10];
    g_row[i] = r;
    g_cur[i] = r;
    g_dinv[i] = rsqrtf(1.0f + (float)g_cnt[i]);
}

// ------------------------------------------------------------ CSR fill
__global__ void k_fill(const void* ei, int E) {
    int e = blockIdx.x * blockDim.x + threadIdx.x;
    if (e >= E) return;
    int is32 = g_is32;
    int s = edge_at(ei, e, is32);
    int d = edge_at(ei, (long long)E + e, is32);
    int pos = atomicAdd(&g_cur[d], 1);
    float w = g_dinv[s] * g_dinv[d];
    g_edge[pos] = make_int2(s, __float_as_int(w));
}

// ------------------------------------------------------------ fused GEMM1 + degree histogram
// Blocks [0, g1b): h = x @ W1 (64-row k-major tile, FFMA2), epilogue converts to fp16.
// Blocks [g1b, +DEGB): grid-stride degree histogram (independent).
__global__ void k_gemm1deg(const float* __restrict__ x, const float* __restrict__ W,
                           const void* ei, int N, int E, int g1b) {
    if (blockIdx.x >= g1b) {
        int is32 = g_is32;
        int base   = (blockIdx.x - g1b) * blockDim.x + threadIdx.x;
        int stride = DEGB * blockDim.x;
        for (int i = base; i < E; i += stride) {
            int d = edge_at(ei, (long long)E + i, is32);
            atomicAdd(&g_cnt[d], 1);
        }
        return;
    }

    __shared__ float xs[128][66];      // [k][row], stride 66 (8B-aligned pairs)
    int row0 = blockIdx.x * 64;
    int tid  = threadIdx.x;

    for (int i = tid; i < 64 * 128; i += 256) {
        int k = i & 127, r = i >> 7;
        int gr = row0 + r;
        xs[k][r] = (gr < N) ? x[(size_t)gr * 128 + k] : 0.f;
    }
    __syncthreads();

    int tx = tid & 31;       // cols tx*4..tx*4+3
    int ty = tid >> 5;       // rows ty*8..ty*8+7 (4 row-pairs)
    unsigned long long acc[4][4];
#pragma unroll
    for (int rp = 0; rp < 4; rp++)
#pragma unroll
        for (int c = 0; c < 4; c++) acc[rp][c] = 0ull;

    const float4* W4 = (const float4*)W;
#pragma unroll 4
    for (int k = 0; k < 128; k++) {
        float4 w = __ldg(&W4[k * 32 + tx]);
        unsigned long long wp[4];
        wp[0] = pk2(w.x, w.x); wp[1] = pk2(w.y, w.y);
        wp[2] = pk2(w.z, w.z); wp[3] = pk2(w.w, w.w);
#pragma unroll
        for (int rp = 0; rp < 4; rp++) {
            unsigned long long xv = *(const unsigned long long*)&xs[k][ty * 8 + rp * 2];
            fma2(acc[rp][0], xv, wp[0]);
            fma2(acc[rp][1], xv, wp[1]);
            fma2(acc[rp][2], xv, wp[2]);
            fma2(acc[rp][3], xv, wp[3]);
        }
    }

    uint2* h16 = (uint2*)g_h;          // row = 32 uint2 (128 halves)
#pragma unroll
    for (int rp = 0; rp < 4; rp++) {
        float2 c0 = upk2(acc[rp][0]), c1 = upk2(acc[rp][1]);
        float2 c2 = upk2(acc[rp][2]), c3 = upk2(acc[rp][3]);
        int gr0 = row0 + ty * 8 + rp * 2;
        if (gr0 < N) {
            half2 lo = __floats2half2_rn(c0.x, c1.x);
            half2 hi = __floats2half2_rn(c2.x, c3.x);
            h16[(size_t)gr0 * 32 + tx] = make_uint2(*(uint32_t*)&lo, *(uint32_t*)&hi);
        }
        if (gr0 + 1 < N) {
            half2 lo = __floats2half2_rn(c0.y, c1.y);
            half2 hi = __floats2half2_rn(c2.y, c3.y);
            h16[(size_t)(gr0 + 1) * 32 + tx] = make_uint2(*(uint32_t*)&lo, *(uint32_t*)&hi);
        }
    }
}

// ------------------------------------------------------------ agg layer 1 (warp/node, shfl-batched, fp16 gathers)
__global__ void k_agg1(const float* __restrict__ b1, int N) {
    int lane = threadIdx.x & 31;
    int node = (blockIdx.x * blockDim.x + threadIdx.x) >> 5;
    if (node >= N) return;
    const uint2* __restrict__ h16 = (const uint2*)g_h;

    float di = g_dinv[node];
    float4 acc = h4f(h16[(size_t)node * 32 + lane]);
    float sw = di * di;
    acc.x *= sw; acc.y *= sw; acc.z *= sw; acc.w *= sw;

    int beg = g_row[node];
    int deg = g_cnt[node];

    for (int base = 0; base < deg; base += 32) {
        int rem = deg - base;
        int m = rem < 32 ? rem : 32;
        int2 ew = make_int2(0, 0);
        if (lane < m) ew = __ldg(&g_edge[beg + base + lane]);
#pragma unroll 8
        for (int t = 0; t < m; t++) {
            int   s = __shfl_sync(0xFFFFFFFFu, ew.x, t);
            float w = __int_as_float(__shfl_sync(0xFFFFFFFFu, ew.y, t));
            float4 v = h4f(h16[(size_t)s * 32 + lane]);
            acc.x += v.x * w; acc.y += v.y * w;
            acc.z += v.z * w; acc.w += v.w * w;
        }
    }
    float4 b = ((const float4*)b1)[lane];
    acc.x = fmaxf(acc.x + b.x, 0.f);
    acc.y = fmaxf(acc.y + b.y, 0.f);
    acc.z = fmaxf(acc.z + b.z, 0.f);
    acc.w = fmaxf(acc.w + b.w, 0.f);
    ((float4*)g_hb)[(size_t)node * 32 + lane] = acc;
}

// ------------------------------------------------------------ GEMM2: h2 = hb @ W2 [N,128]x[128,64], fp16 epilogue
__global__ void k_gemm2(const float* __restrict__ W, int N) {
    __shared__ float xs[128][66];
    int row0 = blockIdx.x * 64;
    int tid  = threadIdx.x;

    for (int i = tid; i < 64 * 128; i += 256) {
        int k = i & 127, r = i >> 7;
        int gr = row0 + r;
        xs[k][r] = (gr < N) ? g_hb[(size_t)gr * 128 + k] : 0.f;
    }
    __syncthreads();

    int tx = tid & 15;       // cols tx*4..tx*4+3 (64 cols)
    int ty = tid >> 4;       // rows ty*4..ty*4+3 (2 row-pairs)
    unsigned long long acc[2][4];
#pragma unroll
    for (int rp = 0; rp < 2; rp++)
#pragma unroll
        for (int c = 0; c < 4; c++) acc[rp][c] = 0ull;

    const float4* W4 = (const float4*)W;
#pragma unroll 4
    for (int k = 0; k < 128; k++) {
        float4 w = __ldg(&W4[k * 16 + tx]);
        unsigned long long wp[4];
        wp[0] = pk2(w.x, w.x); wp[1] = pk2(w.y, w.y);
        wp[2] = pk2(w.z, w.z); wp[3] = pk2(w.w, w.w);
#pragma unroll
        for (int rp = 0; rp < 2; rp++) {
            unsigned long long xv = *(const unsigned long long*)&xs[k][ty * 4 + rp * 2];
            fma2(acc[rp][0], xv, wp[0]);
            fma2(acc[rp][1], xv, wp[1]);
            fma2(acc[rp][2], xv, wp[2]);
            fma2(acc[rp][3], xv, wp[3]);
        }
    }

    uint2* o16 = (uint2*)g_h2;         // row = 16 uint2 (64 halves)
#pragma unroll
    for (int rp = 0; rp < 2; rp++) {
        float2 c0 = upk2(acc[rp][0]), c1 = upk2(acc[rp][1]);
        float2 c2 = upk2(acc[rp][2]), c3 = upk2(acc[rp][3]);
        int gr0 = row0 + ty * 4 + rp * 2;
        if (gr0 < N) {
            half2 lo = __floats2half2_rn(c0.x, c1.x);
            half2 hi = __floats2half2_rn(c2.x, c3.x);
            o16[(size_t)gr0 * 16 + tx] = make_uint2(*(uint32_t*)&lo, *(uint32_t*)&hi);
        }
        if (gr0 + 1 < N) {
            half2 lo = __floats2half2_rn(c0.y, c1.y);
            half2 hi = __floats2half2_rn(c2.y, c3.y);
            o16[(size_t)(gr0 + 1) * 16 + tx] = make_uint2(*(uint32_t*)&lo, *(uint32_t*)&hi);
        }
    }
}

// ------------------------------------------------------------ agg layer 2: half-warp per node, fp16 gathers + log_softmax
__global__ void k_agg2(const float* __restrict__ b2, float* __restrict__ out, int N) {
    int tid  = threadIdx.x;
    int lane = tid & 31;
    int half = lane >> 4;
    int hl   = lane & 15;
    int node = (((blockIdx.x * blockDim.x + tid) >> 5) << 1) + half;
    if (node >= N) return;
    unsigned mask = half ? 0xFFFF0000u : 0x0000FFFFu;
    const uint2* __restrict__ h16 = (const uint2*)g_h2;   // row = 16 uint2

    float di = g_dinv[node];
    float4 acc = h4f(h16[(size_t)node * 16 + hl]);
    float sw = di * di;
    acc.x *= sw; acc.y *= sw; acc.z *= sw; acc.w *= sw;

    int beg = g_row[node];
    int deg = g_cnt[node];
    int src0 = half << 4;

    for (int base = 0; base < deg; base += 16) {
        int rem = deg - base;
        int m = rem < 16 ? rem : 16;
        int2 ew = make_int2(0, 0);
        if (hl < m) ew = __ldg(&g_edge[beg + base + hl]);
#pragma unroll 4
        for (int t = 0; t < m; t++) {
            int   s = __shfl_sync(mask, ew.x, src0 + t);
            float w = __int_as_float(__shfl_sync(mask, ew.y, src0 + t));
            float4 v = h4f(h16[(size_t)s * 16 + hl]);
            acc.x += v.x * w; acc.y += v.y * w;
            acc.z += v.z * w; acc.w += v.w * w;
        }
    }
    float4 b = ((const float4*)b2)[hl];
    acc.x += b.x; acc.y += b.y; acc.z += b.z; acc.w += b.w;

    float m1 = fmaxf(fmaxf(acc.x, acc.y), fmaxf(acc.z, acc.w));
#pragma unroll
    for (int o = 8; o; o >>= 1) m1 = fmaxf(m1, __shfl_xor_sync(mask, m1, o));
    float s = __expf(acc.x - m1) + __expf(acc.y - m1) + __expf(acc.z - m1) + __expf(acc.w - m1);
#pragma unroll
    for (int o = 8; o; o >>= 1) s += __shfl_xor_sync(mask, s, o);
    float lg = m1 + logf(s);
    ((float4*)out)[(size_t)node * 16 + hl] =
        make_float4(acc.x - lg, acc.y - lg, acc.z - lg, acc.w - lg);
}

// ============================================================ launch
extern "C" void kernel_launch(void* const* d_in, const int* in_sizes, int n_in,
                              void* d_out, int out_size) {
    const float* x  = (const float*)d_in[0];
    const void*  ei = d_in[1];
    const float* W1 = (const float*)d_in[2];
    const float* b1 = (const float*)d_in[3];
    const float* W2 = (const float*)d_in[4];
    const float* b2 = (const float*)d_in[5];
    float* out = (float*)d_out;

    int N = in_sizes[0] / 128;       // 100000
    int E = in_sizes[1] / 2;         // 1600000
    int nscanblk = (N + 1023) / 1024;
    int g1b = (N + 63) / 64;

    // Launch index 3 (ncu's capture slot) = fused GEMM1+deg.
    k_init     <<<(N + 255) / 256, 256>>>(N);
    k_detect   <<<16, 256>>>((const unsigned int*)ei, 2 * E);
    k_scan2    <<<1, 32>>>(0);                       // no-op slot filler
    k_gemm1deg <<<g1b + DEGB, 256>>>(x, W1, ei, N, E, g1b);
    k_scan1    <<<nscanblk, 1024>>>(N);
    k_scan2    <<<1, 32>>>(nscanblk);
    k_scan3    <<<(N + 255) / 256, 256>>>(N);
    k_fill     <<<(E + 255) / 256, 256>>>(ei, E);
    k_agg1     <<<(N + 7) / 8, 256>>>(b1, N);
    k_gemm2    <<<(N + 63) / 64, 256>>>(W2, N);
    k_agg2     <<<(N / 2 + 7) / 8, 256>>>(b2, out, N);
}

// round 16
// speedup vs baseline: 2.2515x; 1.4279x over previous
#include <cuda_runtime.h>
#include <cuda_fp16.h>
#include <cstdint>

// GCN 2-layer: out = log_softmax( A * relu(A * (x@W1) + b1) @ W2 + b2 )
// CSR gather aggregation (no atomics). GEMMs on tensor cores via base-PTX
// mma.sync.m16n8k16 (f16 in, f32 accum). All gather tensors fp16.

#define MAXN 100000
#define MAXE 1600000
#define DEGB 512            // aux blocks on gemm1 launch for degree histogram

__device__ __align__(16) float g_dinv[MAXN];
__device__ int   g_cnt [MAXN];
__device__ int   g_row [MAXN];
__device__ int   g_cur [MAXN];
__device__ int   g_bsum[128];
__device__ __align__(16) int2   g_edge[MAXE];        // {src, w_bits} sorted by dst
__device__ __align__(16) __half g_h  [MAXN * 128];   // x@W1 (fp16)
__device__ __align__(16) __half g_hb [MAXN * 128];   // relu(A*h + b1) (fp16)
__device__ __align__(16) __half g_h2 [MAXN * 64];    // hb@W2 (fp16)
__device__ int g_is32;

__device__ __forceinline__ int edge_at(const void* ei, long long pos, int is32) {
    if (is32) return ((const int*)ei)[pos];
    return (int)(((const long long*)ei)[pos]);
}

// ---- mma.sync helpers (base PTX, sm_75+) ----
__device__ __forceinline__ uint32_t cvta_sm(const void* p) {
    uint32_t a;
    asm("{ .reg .u64 t; cvta.to.shared.u64 t, %1; cvt.u32.u64 %0, t; }" : "=r"(a) : "l"(p));
    return a;
}
__device__ __forceinline__ void ldmx4(uint32_t* r, uint32_t a) {
    asm volatile("ldmatrix.sync.aligned.m8n8.x4.shared.b16 {%0,%1,%2,%3}, [%4];"
                 : "=r"(r[0]), "=r"(r[1]), "=r"(r[2]), "=r"(r[3]) : "r"(a));
}
__device__ __forceinline__ void ldmx2t(uint32_t* r, uint32_t a) {
    asm volatile("ldmatrix.sync.aligned.m8n8.x2.trans.shared.b16 {%0,%1}, [%2];"
                 : "=r"(r[0]), "=r"(r[1]) : "r"(a));
}
__device__ __forceinline__ void mma16816(float* d, const uint32_t* a, const uint32_t* b) {
    asm volatile("mma.sync.aligned.m16n8k16.row.col.f32.f16.f16.f32 "
                 "{%0,%1,%2,%3}, {%4,%5,%6,%7}, {%8,%9}, {%0,%1,%2,%3};"
                 : "+f"(d[0]), "+f"(d[1]), "+f"(d[2]), "+f"(d[3])
                 : "r"(a[0]), "r"(a[1]), "r"(a[2]), "r"(a[3]), "r"(b[0]), "r"(b[1]));
}
// float4 -> 4 packed halves
__device__ __forceinline__ uint2 f4h(float4 v) {
    half2 lo = __floats2half2_rn(v.x, v.y);
    half2 hi = __floats2half2_rn(v.z, v.w);
    return make_uint2(*(uint32_t*)&lo, *(uint32_t*)&hi);
}
// 4 packed halves -> float4
__device__ __forceinline__ float4 h4f(uint2 v) {
    float2 a = __half22float2(*(half2*)&v.x);
    float2 b = __half22float2(*(half2*)&v.y);
    return make_float4(a.x, a.y, b.x, b.y);
}

// ------------------------------------------------------------ init / dtype detect
__global__ void k_init(int n) {
    int i = blockIdx.x * blockDim.x + threadIdx.x;
    if (i < n) g_cnt[i] = 0;
    if (i == 0) g_is32 = 0;
}

__global__ void k_detect(const unsigned int* e, int nwords) {
    int i = blockIdx.x * blockDim.x + threadIdx.x;
    int idx = 2 * i + 1;
    if (i < 4096 && idx < nwords && e[idx] != 0u) atomicOr(&g_is32, 1);
}

// ------------------------------------------------------------ prefix scan
__global__ void k_scan1(int n) {
    __shared__ int sm[1024];
    int tid = threadIdx.x;
    int i = blockIdx.x * 1024 + tid;
    int v = (i < n) ? g_cnt[i] : 0;
    sm[tid] = v;
    __syncthreads();
#pragma unroll
    for (int o = 1; o < 1024; o <<= 1) {
        int t = (tid >= o) ? sm[tid - o] : 0;
        __syncthreads();
        sm[tid] += t;
        __syncthreads();
    }
    if (i < n) g_row[i] = sm[tid] - v;
    if (tid == 1023) g_bsum[blockIdx.x] = sm[tid];
}

__global__ void k_scan2(int nb) {
    if (threadIdx.x == 0) {
        int acc = 0;
        for (int b = 0; b < nb; b++) { int t = g_bsum[b]; g_bsum[b] = acc; acc += t; }
    }
}

__global__ void k_scan3(int n) {
    int i = blockIdx.x * blockDim.x + threadIdx.x;
    if (i >= n) return;
    int r = g_row[i] + g_bsum[i >> 10];
    g_row[i] = r;
    g_cur[i] = r;
    g_dinv[i] = rsqrtf(1.0f + (float)g_cnt[i]);
}

// ------------------------------------------------------------ CSR fill
__global__ void k_fill(const void* ei, int E) {
    int e = blockIdx.x * blockDim.x + threadIdx.x;
    if (e >= E) return;
    int is32 = g_is32;
    int s = edge_at(ei, e, is32);
    int d = edge_at(ei, (long long)E + e, is32);
    int pos = atomicAdd(&g_cur[d], 1);
    float w = g_dinv[s] * g_dinv[d];
    g_edge[pos] = make_int2(s, __float_as_int(w));
}

// ------------------------------------------------------------ GEMM1 (tensor core) + degree histogram
// Blocks [0, g1b): 64-row x 128-col tile of h = x @ W1, mma.sync m16n8k16.
// Blocks [g1b, +DEGB): grid-stride degree histogram.
#define AST 136                      // smem stride in halves (pad 8) — conflict-free ldmatrix
__global__ void k_gemm1deg(const float* __restrict__ x, const float* __restrict__ W,
                           const void* ei, int N, int E, int g1b) {
    if (blockIdx.x >= g1b) {
        int is32 = g_is32;
        int base   = (blockIdx.x - g1b) * blockDim.x + threadIdx.x;
        int stride = DEGB * blockDim.x;
        for (int i = base; i < E; i += stride) {
            int d = edge_at(ei, (long long)E + i, is32);
            atomicAdd(&g_cnt[d], 1);
        }
        return;
    }

    extern __shared__ __half smh[];
    __half* As = smh;                // [64 m][128 k], stride AST
    __half* Bs = smh + 64 * AST;     // [128 k][128 n], stride AST
    int row0 = blockIdx.x * 64;
    int tid  = threadIdx.x;
    const float4* x4 = (const float4*)x;
    const float4* W4 = (const float4*)W;

    for (int i = tid; i < 64 * 32; i += 256) {          // A: x rows -> fp16
        int r = i >> 5, c4 = i & 31;
        int gr = row0 + r;
        float4 v = (gr < N) ? x4[(size_t)gr * 32 + c4] : make_float4(0.f, 0.f, 0.f, 0.f);
        *(uint2*)&As[r * AST + c4 * 4] = f4h(v);
    }
    for (int i = tid; i < 128 * 32; i += 256) {         // B: W1 [k][n] -> fp16
        int k = i >> 5, c4 = i & 31;
        *(uint2*)&Bs[k * AST + c4 * 4] = f4h(W4[k * 32 + c4]);
    }
    __syncthreads();

    int lane = tid & 31, wid = tid >> 5;
    int mband = wid & 3;             // 4 bands of 16 rows
    int n0w   = (wid >> 2) * 64;     // 2 halves of n

    float d[8][4];
#pragma unroll
    for (int nt = 0; nt < 8; nt++)
#pragma unroll
        for (int c = 0; c < 4; c++) d[nt][c] = 0.f;

    uint32_t asb = cvta_sm(As), bsb = cvta_sm(Bs);
    int arow = mband * 16 + (lane & 7) + ((lane >> 3) & 1) * 8;
    int acol = (lane >> 4) * 8;
    int brow = (lane & 7) + ((lane >> 3) & 1) * 8;

#pragma unroll
    for (int ks = 0; ks < 8; ks++) {
        uint32_t ra[4];
        ldmx4(ra, asb + (uint32_t)(arow * AST + ks * 16 + acol) * 2);
#pragma unroll
        for (int nt = 0; nt < 8; nt++) {
            uint32_t rb[2];
            ldmx2t(rb, bsb + (uint32_t)((ks * 16 + brow) * AST + n0w + nt * 8) * 2);
            mma16816(d[nt], ra, rb);
        }
    }

    int g = lane >> 2, t = lane & 3;
    uint32_t* h32 = (uint32_t*)g_h;                     // row = 64 uint32
#pragma unroll
    for (int nt = 0; nt < 8; nt++) {
        int col = (n0w >> 1) + nt * 4 + t;
        int r0 = row0 + mband * 16 + g;
        if (r0 < N) {
            half2 v = __floats2half2_rn(d[nt][0], d[nt][1]);
            h32[(size_t)r0 * 64 + col] = *(uint32_t*)&v;
        }
        if (r0 + 8 < N) {
            half2 v = __floats2half2_rn(d[nt][2], d[nt][3]);
            h32[(size_t)(r0 + 8) * 64 + col] = *(uint32_t*)&v;
        }
    }
}

// ------------------------------------------------------------ agg layer 1 (warp/node, shfl-batched, fp16)
__global__ void k_agg1(const float* __restrict__ b1, int N) {
    int lane = threadIdx.x & 31;
    int node = (blockIdx.x * blockDim.x + threadIdx.x) >> 5;
    if (node >= N) return;
    const uint2* __restrict__ h16 = (const uint2*)g_h;

    float di = g_dinv[node];
    float4 acc = h4f(h16[(size_t)node * 32 + lane]);
    float sw = di * di;
    acc.x *= sw; acc.y *= sw; acc.z *= sw; acc.w *= sw;

    int beg = g_row[node];
    int deg = g_cnt[node];

    for (int base = 0; base < deg; base += 32) {
        int rem = deg - base;
        int m = rem < 32 ? rem : 32;
        int2 ew = make_int2(0, 0);
        if (lane < m) ew = __ldg(&g_edge[beg + base + lane]);
#pragma unroll 8
        for (int t = 0; t < m; t++) {
            int   s = __shfl_sync(0xFFFFFFFFu, ew.x, t);
            float w = __int_as_float(__shfl_sync(0xFFFFFFFFu, ew.y, t));
            float4 v = h4f(h16[(size_t)s * 32 + lane]);
            acc.x += v.x * w; acc.y += v.y * w;
            acc.z += v.z * w; acc.w += v.w * w;
        }
    }
    float4 b = ((const float4*)b1)[lane];
    acc.x = fmaxf(acc.x + b.x, 0.f);
    acc.y = fmaxf(acc.y + b.y, 0.f);
    acc.z = fmaxf(acc.z + b.z, 0.f);
    acc.w = fmaxf(acc.w + b.w, 0.f);
    ((uint2*)g_hb)[(size_t)node * 32 + lane] = f4h(acc);
}

// ------------------------------------------------------------ GEMM2 (tensor core): h2 = hb @ W2 [N,128]x[128,64]
#define BST 72
__global__ void k_gemm2(const float* __restrict__ W, int N) {
    __shared__ __half As[64 * AST];      // [64 m][128 k]
    __shared__ __half Bs[128 * BST];     // [128 k][64 n]
    int row0 = blockIdx.x * 64;
    int tid  = threadIdx.x;
    const uint2* hb16 = (const uint2*)g_hb;
    const float4* W4 = (const float4*)W;

    for (int i = tid; i < 64 * 32; i += 256) {          // A: hb rows (already fp16)
        int r = i >> 5, c4 = i & 31;
        int gr = row0 + r;
        uint2 v = (gr < N) ? hb16[(size_t)gr * 32 + c4] : make_uint2(0u, 0u);
        *(uint2*)&As[r * AST + c4 * 4] = v;
    }
    for (int i = tid; i < 128 * 16; i += 256) {         // B: W2 [k][n] -> fp16
        int k = i >> 4, c4 = i & 15;
        *(uint2*)&Bs[k * BST + c4 * 4] = f4h(W4[k * 16 + c4]);
    }
    __syncthreads();

    int lane = tid & 31, wid = tid >> 5;
    int mband = wid & 3;
    int n0w   = (wid >> 2) * 32;     // 2 halves of n=64

    float d[4][4];
#pragma unroll
    for (int nt = 0; nt < 4; nt++)
#pragma unroll
        for (int c = 0; c < 4; c++) d[nt][c] = 0.f;

    uint32_t asb = cvta_sm(As), bsb = cvta_sm(Bs);
    int arow = mband * 16 + (lane & 7) + ((lane >> 3) & 1) * 8;
    int acol = (lane >> 4) * 8;
    int brow = (lane & 7) + ((lane >> 3) & 1) * 8;

#pragma unroll
    for (int ks = 0; ks < 8; ks++) {
        uint32_t ra[4];
        ldmx4(ra, asb + (uint32_t)(arow * AST + ks * 16 + acol) * 2);
#pragma unroll
        for (int nt = 0; nt < 4; nt++) {
            uint32_t rb[2];
            ldmx2t(rb, bsb + (uint32_t)((ks * 16 + brow) * BST + n0w + nt * 8) * 2);
            mma16816(d[nt], ra, rb);
        }
    }

    int g = lane >> 2, t = lane & 3;
    uint32_t* o32 = (uint32_t*)g_h2;                    // row = 32 uint32
#pragma unroll
    for (int nt = 0; nt < 4; nt++) {
        int col = (n0w >> 1) + nt * 4 + t;
        int r0 = row0 + mband * 16 + g;
        if (r0 < N) {
            half2 v = __floats2half2_rn(d[nt][0], d[nt][1]);
            o32[(size_t)r0 * 32 + col] = *(uint32_t*)&v;
        }
        if (r0 + 8 < N) {
            half2 v = __floats2half2_rn(d[nt][2], d[nt][3]);
            o32[(size_t)(r0 + 8) * 32 + col] = *(uint32_t*)&v;
        }
    }
}

// ------------------------------------------------------------ agg layer 2: half-warp per node, fp16 + log_softmax
__global__ void k_agg2(const float* __restrict__ b2, float* __restrict__ out, int N) {
    int tid  = threadIdx.x;
    int lane = tid & 31;
    int half = lane >> 4;
    int hl   = lane & 15;
    int node = (((blockIdx.x * blockDim.x + tid) >> 5) << 1) + half;
    if (node >= N) return;
    unsigned mask = half ? 0xFFFF0000u : 0x0000FFFFu;
    const uint2* __restrict__ h16 = (const uint2*)g_h2;   // row = 16 uint2

    float di = g_dinv[node];
    float4 acc = h4f(h16[(size_t)node * 16 + hl]);
    float sw = di * di;
    acc.x *= sw; acc.y *= sw; acc.z *= sw; acc.w *= sw;

    int beg = g_row[node];
    int deg = g_cnt[node];
    int src0 = half << 4;

    for (int base = 0; base < deg; base += 16) {
        int rem = deg - base;
        int m = rem < 16 ? rem : 16;
        int2 ew = make_int2(0, 0);
        if (hl < m) ew = __ldg(&g_edge[beg + base + hl]);
#pragma unroll 4
        for (int t = 0; t < m; t++) {
            int   s = __shfl_sync(mask, ew.x, src0 + t);
            float w = __int_as_float(__shfl_sync(mask, ew.y, src0 + t));
            float4 v = h4f(h16[(size_t)s * 16 + hl]);
            acc.x += v.x * w; acc.y += v.y * w;
            acc.z += v.z * w; acc.w += v.w * w;
        }
    }
    float4 b = ((const float4*)b2)[hl];
    acc.x += b.x; acc.y += b.y; acc.z += b.z; acc.w += b.w;

    float m1 = fmaxf(fmaxf(acc.x, acc.y), fmaxf(acc.z, acc.w));
#pragma unroll
    for (int o = 8; o; o >>= 1) m1 = fmaxf(m1, __shfl_xor_sync(mask, m1, o));
    float s = __expf(acc.x - m1) + __expf(acc.y - m1) + __expf(acc.z - m1) + __expf(acc.w - m1);
#pragma unroll
    for (int o = 8; o; o >>= 1) s += __shfl_xor_sync(mask, s, o);
    float lg = m1 + logf(s);
    ((float4*)out)[(size_t)node * 16 + hl] =
        make_float4(acc.x - lg, acc.y - lg, acc.z - lg, acc.w - lg);
}

// ============================================================ launch
extern "C" void kernel_launch(void* const* d_in, const int* in_sizes, int n_in,
                              void* d_out, int out_size) {
    const float* x  = (const float*)d_in[0];
    const void*  ei = d_in[1];
    const float* W1 = (const float*)d_in[2];
    const float* b1 = (const float*)d_in[3];
    const float* W2 = (const float*)d_in[4];
    const float* b2 = (const float*)d_in[5];
    float* out = (float*)d_out;

    int N = in_sizes[0] / 128;       // 100000
    int E = in_sizes[1] / 2;         // 1600000
    int nscanblk = (N + 1023) / 1024;
    int g1b = (N + 63) / 64;
    const int G1SM = (64 * AST + 128 * AST) * 2;   // 52224 B dynamic smem

    static int smem_set = 0;
    if (!smem_set) {
        cudaFuncSetAttribute(k_gemm1deg, cudaFuncAttributeMaxDynamicSharedMemorySize, G1SM);
        smem_set = 1;
    }

    // Launch index 3 (ncu's capture slot) = fused GEMM1+deg.
    k_init     <<<(N + 255) / 256, 256>>>(N);
    k_detect   <<<16, 256>>>((const unsigned int*)ei, 2 * E);
    k_scan2    <<<1, 32>>>(0);                       // no-op slot filler
    k_gemm1deg <<<g1b + DEGB, 256, G1SM>>>(x, W1, ei, N, E, g1b);
    k_scan1    <<<nscanblk, 1024>>>(N);
    k_scan2    <<<1, 32>>>(nscanblk);
    k_scan3    <<<(N + 255) / 256, 256>>>(N);
    k_fill     <<<(E + 255) / 256, 256>>>(ei, E);
    k_agg1     <<<(N + 7) / 8, 256>>>(b1, N);
    k_gemm2    <<<(N + 63) / 64, 256>>>(W2, N);
    k_agg2     <<<(N / 2 + 7) / 8, 256>>>(b2, out, N);
}